// round 14
// baseline (speedup 1.0000x reference)
#include <cuda_runtime.h>
#include <cuda_bf16.h>
#include <cstdint>

// RWKV TimeMix on GB300 (compute_103-safe tensor path):
//   mix(bf16 split, K-blocked+SW64-swizzled layout) -> 3x HMMA GEMM (bulk-copy
//   pipelined, occupancy 2) -> WKV 3-phase parallel scan -> HMMA output GEMM.
// GEMM: D[m,d] = sum_c A[m,c]*W[d,c]; fp32 accuracy via bf16 3-term split:
//   D = Ah*Wh + Ah*Wl + Al*Wh     (lo*lo dropped, ~2^-18 relative)
// Blocked layout: chunk ck holds a contiguous [rows x 32] tile with 64B rows,
// SW64 swizzle PRE-APPLIED in gmem; one 1D cp.async.bulk per operand per chunk
// lands ldmatrix-ready. KCHUNK=32 keeps stages at 48KB -> 2 CTAs/SM.

#define BB 32
#define TT 256
#define CC 1024
#define MROWS (BB * TT)                 // 8192
#define SZ (BB * TT * CC)               // 8,388,608
#define WSZ (CC * CC)                   // 1,048,576
#define SEG 8
#define SEGLEN (TT / SEG)               // 32
#define NSEGST (BB * SEG * CC)          // 262144

// ------------------------- device scratch (no allocs) -----------------------
__device__ __nv_bfloat16 g_a_hi[3 * SZ];   // blocked+swizzled
__device__ __nv_bfloat16 g_a_lo[3 * SZ];
__device__ __nv_bfloat16 g_w_hi[4 * WSZ];  // blocked+swizzled
__device__ __nv_bfloat16 g_w_lo[4 * WSZ];
__device__ float         g_kvr[3 * SZ];    // linear [m][c]
__device__ __nv_bfloat16 g_y_hi[SZ];       // blocked+swizzled
__device__ __nv_bfloat16 g_y_lo[SZ];
__device__ float g_sca[NSEGST], g_scb[NSEGST], g_sco[NSEGST];
__device__ float g_pa[NSEGST],  g_pb[NSEGST],  g_po[NSEGST];

// ------------------------------ PTX helpers --------------------------------
__device__ __forceinline__ uint32_t smem_u32(const void* p) {
    uint32_t a;
    asm("{ .reg .u64 t; cvta.to.shared.u64 t, %1; cvt.u32.u64 %0, t; }"
        : "=r"(a) : "l"(p));
    return a;
}
__device__ __forceinline__ uint32_t sw64(uint32_t o) {
    return o ^ ((o >> 3) & 0x30);
}
__device__ __forceinline__ void bulk_g2s(uint32_t dst, const void* src,
                                         uint32_t bytes, uint32_t mbar) {
    asm volatile(
        "cp.async.bulk.shared::cluster.global.mbarrier::complete_tx::bytes "
        "[%0], [%1], %2, [%3];"
        :: "r"(dst), "l"(src), "r"(bytes), "r"(mbar) : "memory");
}
#define MBAR_INIT(mb, n) \
    asm volatile("mbarrier.init.shared.b64 [%0], %1;" :: "r"(mb), "r"(n) : "memory")
#define MBAR_EXPECT_TX(mb, bytes) \
    asm volatile("mbarrier.arrive.expect_tx.shared.b64 _, [%0], %1;" \
                 :: "r"(mb), "r"(bytes) : "memory")
#define MBAR_WAIT(mb, par) do {                                                   \
    uint32_t _m = (mb), _p = (par), _d;                                           \
    asm volatile("{ .reg .pred p;"                                                \
        " mbarrier.try_wait.parity.acquire.cta.shared::cta.b64 p, [%1], %2;"      \
        " selp.b32 %0,1,0,p; }" : "=r"(_d) : "r"(_m), "r"(_p) : "memory");        \
    if (!_d) {                                                                    \
        asm volatile("{ .reg .pred P;"                                            \
            "WL_%=: mbarrier.try_wait.parity.acquire.cta.shared::cta.b64 P, [%0], %1, 0x989680;" \
            " @P bra.uni WD_%=;  bra.uni WL_%=;  WD_%=: }"                        \
            :: "r"(_m), "r"(_p) : "memory");                                      \
    }                                                                             \
} while (0)

__device__ __forceinline__ void ldsm4(uint32_t* r, uint32_t a) {
    asm volatile("ldmatrix.sync.aligned.m8n8.x4.shared.b16 {%0,%1,%2,%3}, [%4];"
        : "=r"(r[0]), "=r"(r[1]), "=r"(r[2]), "=r"(r[3]) : "r"(a));
}
__device__ __forceinline__ void mma16816(float* c, const uint32_t* a, const uint32_t* b) {
    asm volatile("mma.sync.aligned.m16n8k16.row.col.f32.bf16.bf16.f32 "
        "{%0,%1,%2,%3}, {%4,%5,%6,%7}, {%8,%9}, {%0,%1,%2,%3};"
        : "+f"(c[0]), "+f"(c[1]), "+f"(c[2]), "+f"(c[3])
        : "r"(a[0]), "r"(a[1]), "r"(a[2]), "r"(a[3]), "r"(b[0]), "r"(b[1]));
}
__device__ __forceinline__ void split2(float a, float b, uint32_t& h2, uint32_t& l2) {
    asm("cvt.rn.bf16x2.f32 %0, %1, %2;" : "=r"(h2) : "f"(b), "f"(a));
    float ha = __uint_as_float(h2 << 16);
    float hb = __uint_as_float(h2 & 0xFFFF0000u);
    asm("cvt.rn.bf16x2.f32 %0, %1, %2;" : "=r"(l2) : "f"(b - hb), "f"(a - ha));
}

// Blocked-layout byte offsets (KCHUNK=32, 64B rows, SW64 baked in).
__device__ __forceinline__ size_t ablk(int m, int c) {     // activations / y
    uint32_t o = (uint32_t)m * 64 + (c & 31) * 2;
    return (size_t)(c >> 5) * (MROWS * 64) + sw64(o);
}
__device__ __forceinline__ size_t wblk(int n, int c) {     // weights
    uint32_t o = (uint32_t)n * 64 + (c & 31) * 2;
    return (size_t)(c >> 5) * (CC * 64) + sw64(o);
}

// ------------------------------ GEMM config --------------------------------
#define CTA_M 256
#define CTA_N 128
#define KCHUNK 32
#define NCHUNK (CC / KCHUNK)       // 32
#define SM_AH 0
#define SM_AL 16384
#define SM_WH 32768
#define SM_WL 40960
#define STAGE 49152
#define CHUNK_BYTES 49152
#define SMEM_BYTES (2 * STAGE + 64)   // 98368  -> 2 CTAs/SM

__device__ __forceinline__ void gemm_mma_body(
    const char* __restrict__ Ahb, const char* __restrict__ Alb,
    const char* __restrict__ Whb, const char* __restrict__ Wlb,
    float* __restrict__ D)
{
    extern __shared__ char smem[];
    const uint32_t sb = smem_u32(smem);
    const uint32_t mbb = sb + 2 * STAGE;       // two 8B mbarriers
    const int tid = threadIdx.x;
    const int wid = tid >> 5;
    const int lane = tid & 31;
    const int wm = wid >> 1;
    const int wn = wid & 1;
    const int gm = blockIdx.y * CTA_M;
    const int gn = blockIdx.x * CTA_N;

    if (tid == 0) { MBAR_INIT(mbb, 1); MBAR_INIT(mbb + 8, 1); }
    __syncthreads();

#define ISSUE(ck, s) do {                                                     \
    uint32_t _mb = mbb + 8 * (s);                                             \
    uint32_t _d  = sb + (s) * STAGE;                                          \
    MBAR_EXPECT_TX(_mb, CHUNK_BYTES);                                         \
    bulk_g2s(_d + SM_AH, Ahb + (size_t)(ck) * (MROWS * 64) + gm * 64, 16384, _mb); \
    bulk_g2s(_d + SM_AL, Alb + (size_t)(ck) * (MROWS * 64) + gm * 64, 16384, _mb); \
    bulk_g2s(_d + SM_WH, Whb + (size_t)(ck) * (CC * 64) + gn * 64, 8192, _mb);     \
    bulk_g2s(_d + SM_WL, Wlb + (size_t)(ck) * (CC * 64) + gn * 64, 8192, _mb);     \
} while (0)

    if (tid == 0) { ISSUE(0, 0); ISSUE(1, 1); }

    float acc[4][8][4];
#pragma unroll
    for (int i = 0; i < 4; i++)
#pragma unroll
        for (int j = 0; j < 8; j++)
#pragma unroll
            for (int q = 0; q < 4; q++) acc[i][j][q] = 0.f;

    const int a_row = wm * 64 + (lane & 7) + ((lane >> 3) & 1) * 8;  // + mi*16
    const int a_kof = (lane >> 4) * 8;                               // + k0
    const int b_row = wn * 64 + lane;                                // + g*32

    for (int ck = 0; ck < NCHUNK; ck++) {
        const int s = ck & 1;
        MBAR_WAIT(mbb + 8 * s, (ck >> 1) & 1);
        const uint32_t s0 = sb + s * STAGE;

#pragma unroll
        for (int k0 = 0; k0 < KCHUNK; k0 += 16) {
            uint32_t ah[4][4], al[4][4];
#pragma unroll
            for (int mi = 0; mi < 4; mi++) {
                uint32_t o = (uint32_t)(a_row + mi * 16) * 64 + (k0 + a_kof) * 2;
                ldsm4(ah[mi], s0 + SM_AH + sw64(o));
                ldsm4(al[mi], s0 + SM_AL + sw64(o));
            }
#pragma unroll
            for (int g = 0; g < 2; g++) {
                uint32_t t0[4], t1[4], u0[4], u1[4];
                uint32_t o0 = (uint32_t)(b_row + g * 32) * 64 + k0 * 2;
                uint32_t o1 = o0 + 16;           // k-half 1
                ldsm4(t0, s0 + SM_WH + sw64(o0));
                ldsm4(t1, s0 + SM_WH + sw64(o1));
                ldsm4(u0, s0 + SM_WL + sw64(o0));
                ldsm4(u1, s0 + SM_WL + sw64(o1));
#pragma unroll
                for (int ss = 0; ss < 4; ss++) {
                    uint32_t bh[2] = { t0[ss], t1[ss] };
                    uint32_t bl[2] = { u0[ss], u1[ss] };
#pragma unroll
                    for (int mi = 0; mi < 4; mi++) {
                        float* a = acc[mi][g * 4 + ss];
                        mma16816(a, ah[mi], bh);
                        mma16816(a, ah[mi], bl);
                        mma16816(a, al[mi], bh);
                    }
                }
            }
        }
        __syncthreads();
        if (ck + 2 < NCHUNK && tid == 0) ISSUE(ck + 2, s);
    }
#undef ISSUE

    const int trow = lane >> 2;
    const int tcol = (lane & 3) * 2;
#pragma unroll
    for (int mi = 0; mi < 4; mi++) {
#pragma unroll
        for (int ni = 0; ni < 8; ni++) {
            float* dp = D + (size_t)(gm + wm * 64 + mi * 16 + trow) * CC
                          + gn + wn * 64 + ni * 8 + tcol;
            float2 v0 = { acc[mi][ni][0], acc[mi][ni][1] };
            float2 v1 = { acc[mi][ni][2], acc[mi][ni][3] };
            *(float2*)dp = v0;
            *(float2*)(dp + 8 * CC) = v1;
        }
    }
}

__global__ __launch_bounds__(256, 2)
void gemm3_mma() {
    const int z = blockIdx.z;
    gemm_mma_body((const char*)g_a_hi + (size_t)z * SZ * 2,
                  (const char*)g_a_lo + (size_t)z * SZ * 2,
                  (const char*)g_w_hi + (size_t)z * WSZ * 2,
                  (const char*)g_w_lo + (size_t)z * WSZ * 2,
                  g_kvr + (size_t)z * SZ);
}

__global__ __launch_bounds__(256, 2)
void gemm_out_mma(float* __restrict__ out) {
    gemm_mma_body((const char*)g_y_hi, (const char*)g_y_lo,
                  (const char*)g_w_hi + (size_t)3 * WSZ * 2,
                  (const char*)g_w_lo + (size_t)3 * WSZ * 2, out);
}

// ------------------------------- mix kernel ---------------------------------
__global__ void mix_kernel(const float* __restrict__ x,
                           const float* __restrict__ tmk,
                           const float* __restrict__ tmv,
                           const float* __restrict__ tmr) {
    const int n4 = SZ / 4;
    int i = blockIdx.x * blockDim.x + threadIdx.x;
    if (i >= n4) return;
    const int cpt = CC / 4;                 // 256 float4 per row
    int c4 = i & (cpt - 1);
    int m  = i >> 8;                        // global row (b*TT + t)
    int t  = m & (TT - 1);
    int c  = c4 * 4;

    const float4* x4 = (const float4*)x;
    float4 xc = x4[i];
    float4 xp = make_float4(0.f, 0.f, 0.f, 0.f);
    if (t != 0) xp = x4[i - cpt];

    const float4 ms[3] = { ((const float4*)tmk)[c4],
                           ((const float4*)tmv)[c4],
                           ((const float4*)tmr)[c4] };
    const size_t off = ablk(m, c);
#pragma unroll
    for (int z = 0; z < 3; z++) {
        float4 mm = ms[z];
        float a = xp.x + mm.x * (xc.x - xp.x);
        float b = xp.y + mm.y * (xc.y - xp.y);
        float c2 = xp.z + mm.z * (xc.z - xp.z);
        float d = xp.w + mm.w * (xc.w - xp.w);
        uint2 h, l;
        split2(a, b, h.x, l.x);
        split2(c2, d, h.y, l.y);
        *(uint2*)((char*)g_a_hi + (size_t)z * SZ * 2 + off) = h;
        *(uint2*)((char*)g_a_lo + (size_t)z * SZ * 2 + off) = l;
    }
}

// --------------------------- weight split kernel ----------------------------
__global__ void wsplit_kernel(const float* __restrict__ Wk, const float* __restrict__ Wv,
                              const float* __restrict__ Wr, const float* __restrict__ Wo) {
    int i = blockIdx.x * blockDim.x + threadIdx.x;
    const int per = WSZ / 4;
    if (i >= 4 * per) return;
    int z = i >> 18;
    int loc = i & (per - 1);
    int n = loc >> 8;
    int c = (loc & 255) * 4;
    const float* W = (z == 0) ? Wk : (z == 1) ? Wv : (z == 2) ? Wr : Wo;
    float4 v = ((const float4*)W)[loc];
    uint2 h, l;
    split2(v.x, v.y, h.x, l.x);
    split2(v.z, v.w, h.y, l.y);
    const size_t off = wblk(n, c);
    *(uint2*)((char*)g_w_hi + (size_t)z * WSZ * 2 + off) = h;
    *(uint2*)((char*)g_w_lo + (size_t)z * WSZ * 2 + off) = l;
}

// ----------------------- WKV: 3-phase parallel scan -------------------------
__global__ void wkv_segA(const float* __restrict__ time_decay) {
    int gid = blockIdx.x * blockDim.x + threadIdx.x;
    if (gid >= NSEGST) return;
    int c = gid & (CC - 1);
    int s = (gid >> 10) & (SEG - 1);
    int b = gid >> 13;

    float w = -__expf(time_decay[c]);
    const float* kk = g_kvr;
    const float* vv = g_kvr + SZ;
    size_t off = ((size_t)(b * TT + s * SEGLEN)) * CC + c;

    float ca = 0.f, cb = 0.f, oo = -1e38f;
#pragma unroll 4
    for (int t = 0; t < SEGLEN; t++, off += CC) {
        float kt = kk[off];
        float vt = vv[off];
        float wo = w + oo;
        float no = fmaxf(wo, kt);
        float A2 = __expf(wo - no);
        float B2 = __expf(kt - no);
        ca = A2 * ca + B2 * vt;
        cb = A2 * cb + B2;
        oo = no;
    }
    g_sca[gid] = ca;
    g_scb[gid] = cb;
    g_sco[gid] = oo;
}

__global__ void wkv_segB(const float* __restrict__ time_decay) {
    int gid = blockIdx.x * blockDim.x + threadIdx.x;
    if (gid >= BB * CC) return;
    int c = gid & (CC - 1);
    int b = gid >> 10;

    float w = -__expf(time_decay[c]);
    float dec = (float)SEGLEN * w;

    float a = 0.f, q = 0.f, oo = -1e38f;
#pragma unroll
    for (int s = 0; s < SEG; s++) {
        int idx = (b * SEG + s) * CC + c;
        g_pa[idx] = a;
        g_pb[idx] = q;
        g_po[idx] = oo;
        float od = oo + dec;
        float co = g_sco[idx];
        float no = fmaxf(od, co);
        float e1 = __expf(od - no);
        float e2 = __expf(co - no);
        a  = e1 * a + e2 * g_sca[idx];
        q  = e1 * q + e2 * g_scb[idx];
        oo = no;
    }
}

__global__ void wkv_segC(const float* __restrict__ time_decay,
                         const float* __restrict__ time_first) {
    int gid = blockIdx.x * blockDim.x + threadIdx.x;
    if (gid >= NSEGST) return;
    int c = gid & (CC - 1);
    int s = (gid >> 10) & (SEG - 1);
    int b = gid >> 13;

    float w = -__expf(time_decay[c]);
    float u = time_first[c];

    const float* kk = g_kvr;
    const float* vv = g_kvr + SZ;
    const float* rr = g_kvr + 2 * (size_t)SZ;

    float p = g_pa[gid];
    float q = g_pb[gid];
    float o = g_po[gid];
    int m0 = b * TT + s * SEGLEN;
    size_t off = (size_t)m0 * CC + c;

#pragma unroll 4
    for (int t = 0; t < SEGLEN; t++, off += CC) {
        float kt = kk[off];
        float vt = vv[off];
        float rt = rr[off];

        float uk = u + kt;
        float no = fmaxf(o, uk);
        float eA = __expf(o - no);
        float eB = __expf(uk - no);
        float y  = __fdividef(eA * p + eB * vt, eA * q + eB);

        float sr = __fdividef(1.f, 1.f + __expf(-rt));
        float f = sr * y;
        __nv_bfloat16 h = __float2bfloat16(f);
        size_t bo = ablk(m0 + t, c);
        *(__nv_bfloat16*)((char*)g_y_hi + bo) = h;
        *(__nv_bfloat16*)((char*)g_y_lo + bo) =
            __float2bfloat16(f - __bfloat162float(h));

        float wo  = w + o;
        float no2 = fmaxf(wo, kt);
        float A2  = __expf(wo - no2);
        float B2  = __expf(kt - no2);
        p = A2 * p + B2 * vt;
        q = A2 * q + B2;
        o = no2;
    }
}

// ---------------------------------------------------------------------------
extern "C" void kernel_launch(void* const* d_in, const int* in_sizes, int n_in,
                              void* d_out, int out_size) {
    const float* x   = (const float*)d_in[0];
    const float* td  = (const float*)d_in[1];
    const float* tf  = (const float*)d_in[2];
    const float* tmk = (const float*)d_in[3];
    const float* tmv = (const float*)d_in[4];
    const float* tmr = (const float*)d_in[5];
    const float* Wk  = (const float*)d_in[6];
    const float* Wv  = (const float*)d_in[7];
    const float* Wr  = (const float*)d_in[8];
    const float* Wo  = (const float*)d_in[9];
    float* out = (float*)d_out;

    static bool attr_set = false;
    if (!attr_set) {
        cudaFuncSetAttribute(gemm3_mma, cudaFuncAttributeMaxDynamicSharedMemorySize, SMEM_BYTES);
        cudaFuncSetAttribute(gemm_out_mma, cudaFuncAttributeMaxDynamicSharedMemorySize, SMEM_BYTES);
        attr_set = true;
    }

    const int n4 = SZ / 4;
    mix_kernel<<<(n4 + 255) / 256, 256>>>(x, tmk, tmv, tmr);
    wsplit_kernel<<<(WSZ + 255) / 256, 256>>>(Wk, Wv, Wr, Wo);

    dim3 g3(CC / CTA_N, MROWS / CTA_M, 3);
    gemm3_mma<<<g3, 256, SMEM_BYTES>>>();

    wkv_segA<<<(NSEGST + 255) / 256, 256>>>(td);
    wkv_segB<<<(BB * CC + 255) / 256, 256>>>(td);
    wkv_segC<<<(NSEGST + 255) / 256, 256>>>(td, tf);

    dim3 go(CC / CTA_N, MROWS / CTA_M, 1);
    gemm_out_mma<<<go, 256, SMEM_BYTES>>>(out);
}

// round 15
// speedup vs baseline: 1.7507x; 1.7507x over previous
#include <cuda_runtime.h>
#include <cuda_bf16.h>
#include <cstdint>

// RWKV TimeMix on GB300 (compute_103-safe tensor path):
//   mix(bf16 split, K-blocked+SW128 layout) -> 3x HMMA GEMM (bulk-copy
//   pipelined, term-major mma order) -> WKV 3-phase parallel scan -> out GEMM.
// GEMM: D[m,d] = sum_c A[m,c]*W[d,c]; fp32 accuracy via bf16 3-term split:
//   D = Ah*Wh + Ah*Wl + Al*Wh     (lo*lo dropped, ~2^-18 relative)
// R13 config (KCHUNK=64, occ 1) + inner loop reordered term-major so each
// accumulator's reuse distance is 16 mmas (was 1) — hides mma latency at
// 2 warps/SMSP. Do NOT use launch_bounds occ 2 (R14 spill regression).

#define BB 32
#define TT 256
#define CC 1024
#define MROWS (BB * TT)                 // 8192
#define SZ (BB * TT * CC)               // 8,388,608
#define WSZ (CC * CC)                   // 1,048,576
#define SEG 8
#define SEGLEN (TT / SEG)               // 32
#define NSEGST (BB * SEG * CC)          // 262144

// ------------------------- device scratch (no allocs) -----------------------
__device__ __nv_bfloat16 g_a_hi[3 * SZ];   // blocked+swizzled
__device__ __nv_bfloat16 g_a_lo[3 * SZ];
__device__ __nv_bfloat16 g_w_hi[4 * WSZ];  // blocked+swizzled
__device__ __nv_bfloat16 g_w_lo[4 * WSZ];
__device__ float         g_kvr[3 * SZ];    // linear [m][c]
__device__ __nv_bfloat16 g_y_hi[SZ];       // blocked+swizzled
__device__ __nv_bfloat16 g_y_lo[SZ];
__device__ float g_sca[NSEGST], g_scb[NSEGST], g_sco[NSEGST];
__device__ float g_pa[NSEGST],  g_pb[NSEGST],  g_po[NSEGST];

// ------------------------------ PTX helpers --------------------------------
__device__ __forceinline__ uint32_t smem_u32(const void* p) {
    uint32_t a;
    asm("{ .reg .u64 t; cvta.to.shared.u64 t, %1; cvt.u32.u64 %0, t; }"
        : "=r"(a) : "l"(p));
    return a;
}
__device__ __forceinline__ uint32_t sw128(uint32_t o) {
    return o ^ ((o >> 3) & 0x70);
}
__device__ __forceinline__ void bulk_g2s(uint32_t dst, const void* src,
                                         uint32_t bytes, uint32_t mbar) {
    asm volatile(
        "cp.async.bulk.shared::cluster.global.mbarrier::complete_tx::bytes "
        "[%0], [%1], %2, [%3];"
        :: "r"(dst), "l"(src), "r"(bytes), "r"(mbar) : "memory");
}
#define MBAR_INIT(mb, n) \
    asm volatile("mbarrier.init.shared.b64 [%0], %1;" :: "r"(mb), "r"(n) : "memory")
#define MBAR_EXPECT_TX(mb, bytes) \
    asm volatile("mbarrier.arrive.expect_tx.shared.b64 _, [%0], %1;" \
                 :: "r"(mb), "r"(bytes) : "memory")
#define MBAR_WAIT(mb, par) do {                                                   \
    uint32_t _m = (mb), _p = (par), _d;                                           \
    asm volatile("{ .reg .pred p;"                                                \
        " mbarrier.try_wait.parity.acquire.cta.shared::cta.b64 p, [%1], %2;"      \
        " selp.b32 %0,1,0,p; }" : "=r"(_d) : "r"(_m), "r"(_p) : "memory");        \
    if (!_d) {                                                                    \
        asm volatile("{ .reg .pred P;"                                            \
            "WL_%=: mbarrier.try_wait.parity.acquire.cta.shared::cta.b64 P, [%0], %1, 0x989680;" \
            " @P bra.uni WD_%=;  bra.uni WL_%=;  WD_%=: }"                        \
            :: "r"(_m), "r"(_p) : "memory");                                      \
    }                                                                             \
} while (0)

__device__ __forceinline__ void ldsm4(uint32_t* r, uint32_t a) {
    asm volatile("ldmatrix.sync.aligned.m8n8.x4.shared.b16 {%0,%1,%2,%3}, [%4];"
        : "=r"(r[0]), "=r"(r[1]), "=r"(r[2]), "=r"(r[3]) : "r"(a));
}
__device__ __forceinline__ void mma16816(float* c, const uint32_t* a, const uint32_t* b) {
    asm volatile("mma.sync.aligned.m16n8k16.row.col.f32.bf16.bf16.f32 "
        "{%0,%1,%2,%3}, {%4,%5,%6,%7}, {%8,%9}, {%0,%1,%2,%3};"
        : "+f"(c[0]), "+f"(c[1]), "+f"(c[2]), "+f"(c[3])
        : "r"(a[0]), "r"(a[1]), "r"(a[2]), "r"(a[3]), "r"(b[0]), "r"(b[1]));
}
__device__ __forceinline__ void split2(float a, float b, uint32_t& h2, uint32_t& l2) {
    asm("cvt.rn.bf16x2.f32 %0, %1, %2;" : "=r"(h2) : "f"(b), "f"(a));
    float ha = __uint_as_float(h2 << 16);
    float hb = __uint_as_float(h2 & 0xFFFF0000u);
    asm("cvt.rn.bf16x2.f32 %0, %1, %2;" : "=r"(l2) : "f"(b - hb), "f"(a - ha));
}

// Blocked-layout byte offsets (KCHUNK=64, 128B rows, SW128 baked in).
__device__ __forceinline__ size_t ablk(int m, int c) {     // activations / y
    uint32_t o = (uint32_t)m * 128 + (c & 63) * 2;
    return (size_t)(c >> 6) * (MROWS * 128) + sw128(o);
}
__device__ __forceinline__ size_t wblk(int n, int c) {     // weights
    uint32_t o = (uint32_t)n * 128 + (c & 63) * 2;
    return (size_t)(c >> 6) * (CC * 128) + sw128(o);
}

// ------------------------------ GEMM config --------------------------------
#define CTA_M 256
#define CTA_N 128
#define KCHUNK 64
#define NCHUNK (CC / KCHUNK)       // 16
#define SM_AH 0
#define SM_AL 32768
#define SM_WH 65536
#define SM_WL 81920
#define STAGE 98304
#define CHUNK_BYTES 98304
#define SMEM_BYTES (2 * STAGE + 64)   // 196672

__device__ __forceinline__ void gemm_mma_body(
    const char* __restrict__ Ahb, const char* __restrict__ Alb,
    const char* __restrict__ Whb, const char* __restrict__ Wlb,
    float* __restrict__ D)
{
    extern __shared__ char smem[];
    const uint32_t sb = smem_u32(smem);
    const uint32_t mbb = sb + 2 * STAGE;       // two 8B mbarriers
    const int tid = threadIdx.x;
    const int wid = tid >> 5;
    const int lane = tid & 31;
    const int wm = wid >> 1;
    const int wn = wid & 1;
    const int gm = blockIdx.y * CTA_M;
    const int gn = blockIdx.x * CTA_N;

    if (tid == 0) { MBAR_INIT(mbb, 1); MBAR_INIT(mbb + 8, 1); }
    __syncthreads();

#define ISSUE(ck, s) do {                                                     \
    uint32_t _mb = mbb + 8 * (s);                                             \
    uint32_t _d  = sb + (s) * STAGE;                                          \
    MBAR_EXPECT_TX(_mb, CHUNK_BYTES);                                         \
    bulk_g2s(_d + SM_AH, Ahb + (size_t)(ck) * (MROWS * 128) + gm * 128, 32768, _mb); \
    bulk_g2s(_d + SM_AL, Alb + (size_t)(ck) * (MROWS * 128) + gm * 128, 32768, _mb); \
    bulk_g2s(_d + SM_WH, Whb + (size_t)(ck) * (CC * 128) + gn * 128, 16384, _mb);    \
    bulk_g2s(_d + SM_WL, Wlb + (size_t)(ck) * (CC * 128) + gn * 128, 16384, _mb);    \
} while (0)

    if (tid == 0) { ISSUE(0, 0); ISSUE(1, 1); }

    float acc[4][8][4];
#pragma unroll
    for (int i = 0; i < 4; i++)
#pragma unroll
        for (int j = 0; j < 8; j++)
#pragma unroll
            for (int q = 0; q < 4; q++) acc[i][j][q] = 0.f;

    const int a_row = wm * 64 + (lane & 7) + ((lane >> 3) & 1) * 8;  // + mi*16
    const int a_kof = (lane >> 4) * 8;                               // + k0
    const int b_row = wn * 64 + lane;                                // + g*32

    for (int ck = 0; ck < NCHUNK; ck++) {
        const int s = ck & 1;
        MBAR_WAIT(mbb + 8 * s, (ck >> 1) & 1);
        const uint32_t s0 = sb + s * STAGE;

#pragma unroll
        for (int k0 = 0; k0 < KCHUNK; k0 += 16) {
            uint32_t ah[4][4], al[4][4];
#pragma unroll
            for (int mi = 0; mi < 4; mi++) {
                uint32_t o = (uint32_t)(a_row + mi * 16) * 128 + (k0 + a_kof) * 2;
                ldsm4(ah[mi], s0 + SM_AH + sw128(o));
                ldsm4(al[mi], s0 + SM_AL + sw128(o));
            }
#pragma unroll
            for (int g = 0; g < 2; g++) {
                uint32_t t0[4], t1[4], u0[4], u1[4];
                uint32_t o0 = (uint32_t)(b_row + g * 32) * 128 + k0 * 2;
                uint32_t o1 = o0 + 16;           // k-half 1
                ldsm4(t0, s0 + SM_WH + sw128(o0));
                ldsm4(t1, s0 + SM_WH + sw128(o1));
                ldsm4(u0, s0 + SM_WL + sw128(o0));
                ldsm4(u1, s0 + SM_WL + sw128(o1));
                // Term-major passes: 16 independent mmas per pass so each
                // accumulator's reuse distance is 16 (was 1) -> latency hidden.
#pragma unroll
                for (int ss = 0; ss < 4; ss++) {          // pass 1: Ah*Wh
                    uint32_t bh[2] = { t0[ss], t1[ss] };
#pragma unroll
                    for (int mi = 0; mi < 4; mi++)
                        mma16816(acc[mi][g * 4 + ss], ah[mi], bh);
                }
#pragma unroll
                for (int ss = 0; ss < 4; ss++) {          // pass 2: Ah*Wl
                    uint32_t bl[2] = { u0[ss], u1[ss] };
#pragma unroll
                    for (int mi = 0; mi < 4; mi++)
                        mma16816(acc[mi][g * 4 + ss], ah[mi], bl);
                }
#pragma unroll
                for (int ss = 0; ss < 4; ss++) {          // pass 3: Al*Wh
                    uint32_t bh[2] = { t0[ss], t1[ss] };
#pragma unroll
                    for (int mi = 0; mi < 4; mi++)
                        mma16816(acc[mi][g * 4 + ss], al[mi], bh);
                }
            }
        }
        __syncthreads();
        if (ck + 2 < NCHUNK && tid == 0) ISSUE(ck + 2, s);
    }
#undef ISSUE

    const int trow = lane >> 2;
    const int tcol = (lane & 3) * 2;
#pragma unroll
    for (int mi = 0; mi < 4; mi++) {
#pragma unroll
        for (int ni = 0; ni < 8; ni++) {
            float* dp = D + (size_t)(gm + wm * 64 + mi * 16 + trow) * CC
                          + gn + wn * 64 + ni * 8 + tcol;
            float2 v0 = { acc[mi][ni][0], acc[mi][ni][1] };
            float2 v1 = { acc[mi][ni][2], acc[mi][ni][3] };
            *(float2*)dp = v0;
            *(float2*)(dp + 8 * CC) = v1;
        }
    }
}

__global__ __launch_bounds__(256, 1)
void gemm3_mma() {
    const int z = blockIdx.z;
    gemm_mma_body((const char*)g_a_hi + (size_t)z * SZ * 2,
                  (const char*)g_a_lo + (size_t)z * SZ * 2,
                  (const char*)g_w_hi + (size_t)z * WSZ * 2,
                  (const char*)g_w_lo + (size_t)z * WSZ * 2,
                  g_kvr + (size_t)z * SZ);
}

__global__ __launch_bounds__(256, 1)
void gemm_out_mma(float* __restrict__ out) {
    gemm_mma_body((const char*)g_y_hi, (const char*)g_y_lo,
                  (const char*)g_w_hi + (size_t)3 * WSZ * 2,
                  (const char*)g_w_lo + (size_t)3 * WSZ * 2, out);
}

// ------------------------------- mix kernel ---------------------------------
__global__ void mix_kernel(const float* __restrict__ x,
                           const float* __restrict__ tmk,
                           const float* __restrict__ tmv,
                           const float* __restrict__ tmr) {
    const int n4 = SZ / 4;
    int i = blockIdx.x * blockDim.x + threadIdx.x;
    if (i >= n4) return;
    const int cpt = CC / 4;                 // 256 float4 per row
    int c4 = i & (cpt - 1);
    int m  = i >> 8;                        // global row (b*TT + t)
    int t  = m & (TT - 1);
    int c  = c4 * 4;

    const float4* x4 = (const float4*)x;
    float4 xc = x4[i];
    float4 xp = make_float4(0.f, 0.f, 0.f, 0.f);
    if (t != 0) xp = x4[i - cpt];

    const float4 ms[3] = { ((const float4*)tmk)[c4],
                           ((const float4*)tmv)[c4],
                           ((const float4*)tmr)[c4] };
    const size_t off = ablk(m, c);
#pragma unroll
    for (int z = 0; z < 3; z++) {
        float4 mm = ms[z];
        float a = xp.x + mm.x * (xc.x - xp.x);
        float b = xp.y + mm.y * (xc.y - xp.y);
        float c2 = xp.z + mm.z * (xc.z - xp.z);
        float d = xp.w + mm.w * (xc.w - xp.w);
        uint2 h, l;
        split2(a, b, h.x, l.x);
        split2(c2, d, h.y, l.y);
        *(uint2*)((char*)g_a_hi + (size_t)z * SZ * 2 + off) = h;
        *(uint2*)((char*)g_a_lo + (size_t)z * SZ * 2 + off) = l;
    }
}

// --------------------------- weight split kernel ----------------------------
__global__ void wsplit_kernel(const float* __restrict__ Wk, const float* __restrict__ Wv,
                              const float* __restrict__ Wr, const float* __restrict__ Wo) {
    int i = blockIdx.x * blockDim.x + threadIdx.x;
    const int per = WSZ / 4;
    if (i >= 4 * per) return;
    int z = i >> 18;
    int loc = i & (per - 1);
    int n = loc >> 8;
    int c = (loc & 255) * 4;
    const float* W = (z == 0) ? Wk : (z == 1) ? Wv : (z == 2) ? Wr : Wo;
    float4 v = ((const float4*)W)[loc];
    uint2 h, l;
    split2(v.x, v.y, h.x, l.x);
    split2(v.z, v.w, h.y, l.y);
    const size_t off = wblk(n, c);
    *(uint2*)((char*)g_w_hi + (size_t)z * WSZ * 2 + off) = h;
    *(uint2*)((char*)g_w_lo + (size_t)z * WSZ * 2 + off) = l;
}

// ----------------------- WKV: 3-phase parallel scan -------------------------
__global__ void wkv_segA(const float* __restrict__ time_decay) {
    int gid = blockIdx.x * blockDim.x + threadIdx.x;
    if (gid >= NSEGST) return;
    int c = gid & (CC - 1);
    int s = (gid >> 10) & (SEG - 1);
    int b = gid >> 13;

    float w = -__expf(time_decay[c]);
    const float* kk = g_kvr;
    const float* vv = g_kvr + SZ;
    size_t off = ((size_t)(b * TT + s * SEGLEN)) * CC + c;

    float ca = 0.f, cb = 0.f, oo = -1e38f;
#pragma unroll 4
    for (int t = 0; t < SEGLEN; t++, off += CC) {
        float kt = kk[off];
        float vt = vv[off];
        float wo = w + oo;
        float no = fmaxf(wo, kt);
        float A2 = __expf(wo - no);
        float B2 = __expf(kt - no);
        ca = A2 * ca + B2 * vt;
        cb = A2 * cb + B2;
        oo = no;
    }
    g_sca[gid] = ca;
    g_scb[gid] = cb;
    g_sco[gid] = oo;
}

__global__ void wkv_segB(const float* __restrict__ time_decay) {
    int gid = blockIdx.x * blockDim.x + threadIdx.x;
    if (gid >= BB * CC) return;
    int c = gid & (CC - 1);
    int b = gid >> 10;

    float w = -__expf(time_decay[c]);
    float dec = (float)SEGLEN * w;

    float a = 0.f, q = 0.f, oo = -1e38f;
#pragma unroll
    for (int s = 0; s < SEG; s++) {
        int idx = (b * SEG + s) * CC + c;
        g_pa[idx] = a;
        g_pb[idx] = q;
        g_po[idx] = oo;
        float od = oo + dec;
        float co = g_sco[idx];
        float no = fmaxf(od, co);
        float e1 = __expf(od - no);
        float e2 = __expf(co - no);
        a  = e1 * a + e2 * g_sca[idx];
        q  = e1 * q + e2 * g_scb[idx];
        oo = no;
    }
}

__global__ void wkv_segC(const float* __restrict__ time_decay,
                         const float* __restrict__ time_first) {
    int gid = blockIdx.x * blockDim.x + threadIdx.x;
    if (gid >= NSEGST) return;
    int c = gid & (CC - 1);
    int s = (gid >> 10) & (SEG - 1);
    int b = gid >> 13;

    float w = -__expf(time_decay[c]);
    float u = time_first[c];

    const float* kk = g_kvr;
    const float* vv = g_kvr + SZ;
    const float* rr = g_kvr + 2 * (size_t)SZ;

    float p = g_pa[gid];
    float q = g_pb[gid];
    float o = g_po[gid];
    int m0 = b * TT + s * SEGLEN;
    size_t off = (size_t)m0 * CC + c;

#pragma unroll 4
    for (int t = 0; t < SEGLEN; t++, off += CC) {
        float kt = kk[off];
        float vt = vv[off];
        float rt = rr[off];

        float uk = u + kt;
        float no = fmaxf(o, uk);
        float eA = __expf(o - no);
        float eB = __expf(uk - no);
        float y  = __fdividef(eA * p + eB * vt, eA * q + eB);

        float sr = __fdividef(1.f, 1.f + __expf(-rt));
        float f = sr * y;
        __nv_bfloat16 h = __float2bfloat16(f);
        size_t bo = ablk(m0 + t, c);
        *(__nv_bfloat16*)((char*)g_y_hi + bo) = h;
        *(__nv_bfloat16*)((char*)g_y_lo + bo) =
            __float2bfloat16(f - __bfloat162float(h));

        float wo  = w + o;
        float no2 = fmaxf(wo, kt);
        float A2  = __expf(wo - no2);
        float B2  = __expf(kt - no2);
        p = A2 * p + B2 * vt;
        q = A2 * q + B2;
        o = no2;
    }
}

// ---------------------------------------------------------------------------
extern "C" void kernel_launch(void* const* d_in, const int* in_sizes, int n_in,
                              void* d_out, int out_size) {
    const float* x   = (const float*)d_in[0];
    const float* td  = (const float*)d_in[1];
    const float* tf  = (const float*)d_in[2];
    const float* tmk = (const float*)d_in[3];
    const float* tmv = (const float*)d_in[4];
    const float* tmr = (const float*)d_in[5];
    const float* Wk  = (const float*)d_in[6];
    const float* Wv  = (const float*)d_in[7];
    const float* Wr  = (const float*)d_in[8];
    const float* Wo  = (const float*)d_in[9];
    float* out = (float*)d_out;

    static bool attr_set = false;
    if (!attr_set) {
        cudaFuncSetAttribute(gemm3_mma, cudaFuncAttributeMaxDynamicSharedMemorySize, SMEM_BYTES);
        cudaFuncSetAttribute(gemm_out_mma, cudaFuncAttributeMaxDynamicSharedMemorySize, SMEM_BYTES);
        attr_set = true;
    }

    const int n4 = SZ / 4;
    mix_kernel<<<(n4 + 255) / 256, 256>>>(x, tmk, tmv, tmr);
    wsplit_kernel<<<(WSZ + 255) / 256, 256>>>(Wk, Wv, Wr, Wo);

    dim3 g3(CC / CTA_N, MROWS / CTA_M, 3);
    gemm3_mma<<<g3, 256, SMEM_BYTES>>>();

    wkv_segA<<<(NSEGST + 255) / 256, 256>>>(td);
    wkv_segB<<<(BB * CC + 255) / 256, 256>>>(td);
    wkv_segC<<<(NSEGST + 255) / 256, 256>>>(td, tf);

    dim3 go(CC / CTA_N, MROWS / CTA_M, 1);
    gemm_out_mma<<<go, 256, SMEM_BYTES>>>(out);
}

// round 16
// speedup vs baseline: 2.5294x; 1.4448x over previous
#include <cuda_runtime.h>
#include <cuda_bf16.h>
#include <cuda_fp16.h>
#include <cstdint>

// RWKV TimeMix on GB300 (compute_103-safe tensor path):
//   mix(fp16, K-blocked+SW128 layout) -> 3x HMMA GEMM (bulk-copy 3-stage
//   pipeline, fp16 2-term split) -> WKV 3-phase parallel scan -> out GEMM.
// GEMM: D[m,d] = sum_c A[m,c]*W[d,c]; accuracy via fp16 2-term split:
//   D = Ah*Wh + Ah*Wl      (dropped Al*W ~ 2^-11/sqrt3 ≈ 2.8e-4 relative)
// A (activations) carried as single fp16; only W needs hi+lo. Cuts mma count
// 33%, operand traffic 33% vs bf16 3-term (R13/R15 config).

#define BB 32
#define TT 256
#define CC 1024
#define MROWS (BB * TT)                 // 8192
#define SZ (BB * TT * CC)               // 8,388,608
#define WSZ (CC * CC)                   // 1,048,576
#define SEG 8
#define SEGLEN (TT / SEG)               // 32
#define NSEGST (BB * SEG * CC)          // 262144

// ------------------------- device scratch (no allocs) -----------------------
__device__ __half g_a_h[3 * SZ];        // xk,xv,xr fp16, blocked+swizzled
__device__ __half g_w_h[4 * WSZ];       // W hi fp16, blocked+swizzled
__device__ __half g_w_l[4 * WSZ];       // W lo fp16, blocked+swizzled
__device__ float  g_kvr[3 * SZ];        // k,v,r fp32, linear [m][c]
__device__ __half g_y_h[SZ];            // gated y fp16, blocked+swizzled
__device__ float g_sca[NSEGST], g_scb[NSEGST], g_sco[NSEGST];
__device__ float g_pa[NSEGST],  g_pb[NSEGST],  g_po[NSEGST];

// ------------------------------ PTX helpers --------------------------------
__device__ __forceinline__ uint32_t smem_u32(const void* p) {
    uint32_t a;
    asm("{ .reg .u64 t; cvta.to.shared.u64 t, %1; cvt.u32.u64 %0, t; }"
        : "=r"(a) : "l"(p));
    return a;
}
__device__ __forceinline__ uint32_t sw128(uint32_t o) {
    return o ^ ((o >> 3) & 0x70);
}
__device__ __forceinline__ void bulk_g2s(uint32_t dst, const void* src,
                                         uint32_t bytes, uint32_t mbar) {
    asm volatile(
        "cp.async.bulk.shared::cluster.global.mbarrier::complete_tx::bytes "
        "[%0], [%1], %2, [%3];"
        :: "r"(dst), "l"(src), "r"(bytes), "r"(mbar) : "memory");
}
#define MBAR_INIT(mb, n) \
    asm volatile("mbarrier.init.shared.b64 [%0], %1;" :: "r"(mb), "r"(n) : "memory")
#define MBAR_EXPECT_TX(mb, bytes) \
    asm volatile("mbarrier.arrive.expect_tx.shared.b64 _, [%0], %1;" \
                 :: "r"(mb), "r"(bytes) : "memory")
#define MBAR_WAIT(mb, par) do {                                                   \
    uint32_t _m = (mb), _p = (par), _d;                                           \
    asm volatile("{ .reg .pred p;"                                                \
        " mbarrier.try_wait.parity.acquire.cta.shared::cta.b64 p, [%1], %2;"      \
        " selp.b32 %0,1,0,p; }" : "=r"(_d) : "r"(_m), "r"(_p) : "memory");        \
    if (!_d) {                                                                    \
        asm volatile("{ .reg .pred P;"                                            \
            "WL_%=: mbarrier.try_wait.parity.acquire.cta.shared::cta.b64 P, [%0], %1, 0x989680;" \
            " @P bra.uni WD_%=;  bra.uni WL_%=;  WD_%=: }"                        \
            :: "r"(_m), "r"(_p) : "memory");                                      \
    }                                                                             \
} while (0)

__device__ __forceinline__ void ldsm4(uint32_t* r, uint32_t a) {
    asm volatile("ldmatrix.sync.aligned.m8n8.x4.shared.b16 {%0,%1,%2,%3}, [%4];"
        : "=r"(r[0]), "=r"(r[1]), "=r"(r[2]), "=r"(r[3]) : "r"(a));
}
__device__ __forceinline__ void mma16816(float* c, const uint32_t* a, const uint32_t* b) {
    asm volatile("mma.sync.aligned.m16n8k16.row.col.f32.f16.f16.f32 "
        "{%0,%1,%2,%3}, {%4,%5,%6,%7}, {%8,%9}, {%0,%1,%2,%3};"
        : "+f"(c[0]), "+f"(c[1]), "+f"(c[2]), "+f"(c[3])
        : "r"(a[0]), "r"(a[1]), "r"(a[2]), "r"(a[3]), "r"(b[0]), "r"(b[1]));
}
// Pack two floats into fp16x2 (memory order: a low, b high).
__device__ __forceinline__ uint32_t pack_h2(float a, float b) {
    uint32_t h;
    asm("cvt.rn.f16x2.f32 %0, %1, %2;" : "=r"(h) : "f"(b), "f"(a));
    return h;
}
// fp16 split of two floats: hi pair + lo pair.
__device__ __forceinline__ void split2h(float a, float b, uint32_t& h2, uint32_t& l2) {
    asm("cvt.rn.f16x2.f32 %0, %1, %2;" : "=r"(h2) : "f"(b), "f"(a));
    float ha = __half2float(__ushort_as_half((unsigned short)(h2 & 0xFFFF)));
    float hb = __half2float(__ushort_as_half((unsigned short)(h2 >> 16)));
    asm("cvt.rn.f16x2.f32 %0, %1, %2;" : "=r"(l2) : "f"(b - hb), "f"(a - ha));
}

// Blocked-layout byte offsets (KCHUNK=64, 128B rows, SW128 baked in).
__device__ __forceinline__ size_t ablk(int m, int c) {     // activations / y
    uint32_t o = (uint32_t)m * 128 + (c & 63) * 2;
    return (size_t)(c >> 6) * (MROWS * 128) + sw128(o);
}
__device__ __forceinline__ size_t wblk(int n, int c) {     // weights
    uint32_t o = (uint32_t)n * 128 + (c & 63) * 2;
    return (size_t)(c >> 6) * (CC * 128) + sw128(o);
}

// ------------------------------ GEMM config --------------------------------
#define CTA_M 256
#define CTA_N 128
#define KCHUNK 64
#define NCHUNK (CC / KCHUNK)       // 16
#define NSTAGE 3
#define SM_AH 0
#define SM_WH 32768
#define SM_WL 49152
#define STAGE 65536
#define CHUNK_BYTES 65536
#define SMEM_BYTES (NSTAGE * STAGE + 64)   // 196672

__device__ __forceinline__ void gemm_mma_body(
    const char* __restrict__ Ahb,
    const char* __restrict__ Whb, const char* __restrict__ Wlb,
    float* __restrict__ D)
{
    extern __shared__ char smem[];
    const uint32_t sb = smem_u32(smem);
    const uint32_t mbb = sb + NSTAGE * STAGE;   // three 8B mbarriers
    const int tid = threadIdx.x;
    const int wid = tid >> 5;
    const int lane = tid & 31;
    const int wm = wid >> 1;
    const int wn = wid & 1;
    const int gm = blockIdx.y * CTA_M;
    const int gn = blockIdx.x * CTA_N;

    if (tid == 0) { MBAR_INIT(mbb, 1); MBAR_INIT(mbb + 8, 1); MBAR_INIT(mbb + 16, 1); }
    __syncthreads();

#define ISSUE(ck, s) do {                                                     \
    uint32_t _mb = mbb + 8 * (s);                                             \
    uint32_t _d  = sb + (s) * STAGE;                                          \
    MBAR_EXPECT_TX(_mb, CHUNK_BYTES);                                         \
    bulk_g2s(_d + SM_AH, Ahb + (size_t)(ck) * (MROWS * 128) + gm * 128, 32768, _mb); \
    bulk_g2s(_d + SM_WH, Whb + (size_t)(ck) * (CC * 128) + gn * 128, 16384, _mb);    \
    bulk_g2s(_d + SM_WL, Wlb + (size_t)(ck) * (CC * 128) + gn * 128, 16384, _mb);    \
} while (0)

    if (tid == 0) { ISSUE(0, 0); ISSUE(1, 1); ISSUE(2, 2); }

    float acc[4][8][4];
#pragma unroll
    for (int i = 0; i < 4; i++)
#pragma unroll
        for (int j = 0; j < 8; j++)
#pragma unroll
            for (int q = 0; q < 4; q++) acc[i][j][q] = 0.f;

    const int a_row = wm * 64 + (lane & 7) + ((lane >> 3) & 1) * 8;  // + mi*16
    const int a_kof = (lane >> 4) * 8;                               // + k0
    const int b_row = wn * 64 + lane;                                // + g*32

    for (int ck = 0; ck < NCHUNK; ck++) {
        const int s = ck % NSTAGE;
        MBAR_WAIT(mbb + 8 * s, (ck / NSTAGE) & 1);
        const uint32_t s0 = sb + s * STAGE;

#pragma unroll
        for (int k0 = 0; k0 < KCHUNK; k0 += 16) {
            uint32_t ah[4][4];
#pragma unroll
            for (int mi = 0; mi < 4; mi++) {
                uint32_t o = (uint32_t)(a_row + mi * 16) * 128 + (k0 + a_kof) * 2;
                ldsm4(ah[mi], s0 + SM_AH + sw128(o));
            }
#pragma unroll
            for (int g = 0; g < 2; g++) {
                uint32_t t0[4], t1[4], u0[4], u1[4];
                uint32_t o0 = (uint32_t)(b_row + g * 32) * 128 + k0 * 2;
                uint32_t o1 = o0 + 16;           // k-half 1
                ldsm4(t0, s0 + SM_WH + sw128(o0));
                ldsm4(t1, s0 + SM_WH + sw128(o1));
                ldsm4(u0, s0 + SM_WL + sw128(o0));
                ldsm4(u1, s0 + SM_WL + sw128(o1));
#pragma unroll
                for (int ss = 0; ss < 4; ss++) {          // pass 1: Ah*Wh
                    uint32_t bh[2] = { t0[ss], t1[ss] };
#pragma unroll
                    for (int mi = 0; mi < 4; mi++)
                        mma16816(acc[mi][g * 4 + ss], ah[mi], bh);
                }
#pragma unroll
                for (int ss = 0; ss < 4; ss++) {          // pass 2: Ah*Wl
                    uint32_t bl[2] = { u0[ss], u1[ss] };
#pragma unroll
                    for (int mi = 0; mi < 4; mi++)
                        mma16816(acc[mi][g * 4 + ss], ah[mi], bl);
                }
            }
        }
        __syncthreads();
        if (ck + NSTAGE < NCHUNK && tid == 0) ISSUE(ck + NSTAGE, s);
    }
#undef ISSUE

    const int trow = lane >> 2;
    const int tcol = (lane & 3) * 2;
#pragma unroll
    for (int mi = 0; mi < 4; mi++) {
#pragma unroll
        for (int ni = 0; ni < 8; ni++) {
            float* dp = D + (size_t)(gm + wm * 64 + mi * 16 + trow) * CC
                          + gn + wn * 64 + ni * 8 + tcol;
            float2 v0 = { acc[mi][ni][0], acc[mi][ni][1] };
            float2 v1 = { acc[mi][ni][2], acc[mi][ni][3] };
            *(float2*)dp = v0;
            *(float2*)(dp + 8 * CC) = v1;
        }
    }
}

__global__ __launch_bounds__(256, 1)
void gemm3_mma() {
    const int z = blockIdx.z;
    gemm_mma_body((const char*)g_a_h + (size_t)z * SZ * 2,
                  (const char*)g_w_h + (size_t)z * WSZ * 2,
                  (const char*)g_w_l + (size_t)z * WSZ * 2,
                  g_kvr + (size_t)z * SZ);
}

__global__ __launch_bounds__(256, 1)
void gemm_out_mma(float* __restrict__ out) {
    gemm_mma_body((const char*)g_y_h,
                  (const char*)g_w_h + (size_t)3 * WSZ * 2,
                  (const char*)g_w_l + (size_t)3 * WSZ * 2, out);
}

// ------------------------------- mix kernel ---------------------------------
// xk/xv/xr = xx + m*(x-xx), written as single fp16 into blocked layout.
__global__ void mix_kernel(const float* __restrict__ x,
                           const float* __restrict__ tmk,
                           const float* __restrict__ tmv,
                           const float* __restrict__ tmr) {
    const int n4 = SZ / 4;
    int i = blockIdx.x * blockDim.x + threadIdx.x;
    if (i >= n4) return;
    const int cpt = CC / 4;
    int c4 = i & (cpt - 1);
    int m  = i >> 8;
    int t  = m & (TT - 1);
    int c  = c4 * 4;

    const float4* x4 = (const float4*)x;
    float4 xc = x4[i];
    float4 xp = make_float4(0.f, 0.f, 0.f, 0.f);
    if (t != 0) xp = x4[i - cpt];

    const float4 ms[3] = { ((const float4*)tmk)[c4],
                           ((const float4*)tmv)[c4],
                           ((const float4*)tmr)[c4] };
    const size_t off = ablk(m, c);
#pragma unroll
    for (int z = 0; z < 3; z++) {
        float4 mm = ms[z];
        float a  = xp.x + mm.x * (xc.x - xp.x);
        float b  = xp.y + mm.y * (xc.y - xp.y);
        float c2 = xp.z + mm.z * (xc.z - xp.z);
        float d  = xp.w + mm.w * (xc.w - xp.w);
        uint2 h;
        h.x = pack_h2(a, b);
        h.y = pack_h2(c2, d);
        *(uint2*)((char*)g_a_h + (size_t)z * SZ * 2 + off) = h;
    }
}

// --------------------------- weight split kernel ----------------------------
__global__ void wsplit_kernel(const float* __restrict__ Wk, const float* __restrict__ Wv,
                              const float* __restrict__ Wr, const float* __restrict__ Wo) {
    int i = blockIdx.x * blockDim.x + threadIdx.x;
    const int per = WSZ / 4;
    if (i >= 4 * per) return;
    int z = i >> 18;
    int loc = i & (per - 1);
    int n = loc >> 8;
    int c = (loc & 255) * 4;
    const float* W = (z == 0) ? Wk : (z == 1) ? Wv : (z == 2) ? Wr : Wo;
    float4 v = ((const float4*)W)[loc];
    uint2 h, l;
    split2h(v.x, v.y, h.x, l.x);
    split2h(v.z, v.w, h.y, l.y);
    const size_t off = wblk(n, c);
    *(uint2*)((char*)g_w_h + (size_t)z * WSZ * 2 + off) = h;
    *(uint2*)((char*)g_w_l + (size_t)z * WSZ * 2 + off) = l;
}

// ----------------------- WKV: 3-phase parallel scan -------------------------
__global__ void wkv_segA(const float* __restrict__ time_decay) {
    int gid = blockIdx.x * blockDim.x + threadIdx.x;
    if (gid >= NSEGST) return;
    int c = gid & (CC - 1);
    int s = (gid >> 10) & (SEG - 1);
    int b = gid >> 13;

    float w = -__expf(time_decay[c]);
    const float* kk = g_kvr;
    const float* vv = g_kvr + SZ;
    size_t off = ((size_t)(b * TT + s * SEGLEN)) * CC + c;

    float ca = 0.f, cb = 0.f, oo = -1e38f;
#pragma unroll 4
    for (int t = 0; t < SEGLEN; t++, off += CC) {
        float kt = kk[off];
        float vt = vv[off];
        float wo = w + oo;
        float no = fmaxf(wo, kt);
        float A2 = __expf(wo - no);
        float B2 = __expf(kt - no);
        ca = A2 * ca + B2 * vt;
        cb = A2 * cb + B2;
        oo = no;
    }
    g_sca[gid] = ca;
    g_scb[gid] = cb;
    g_sco[gid] = oo;
}

__global__ void wkv_segB(const float* __restrict__ time_decay) {
    int gid = blockIdx.x * blockDim.x + threadIdx.x;
    if (gid >= BB * CC) return;
    int c = gid & (CC - 1);
    int b = gid >> 10;

    float w = -__expf(time_decay[c]);
    float dec = (float)SEGLEN * w;

    float a = 0.f, q = 0.f, oo = -1e38f;
#pragma unroll
    for (int s = 0; s < SEG; s++) {
        int idx = (b * SEG + s) * CC + c;
        g_pa[idx] = a;
        g_pb[idx] = q;
        g_po[idx] = oo;
        float od = oo + dec;
        float co = g_sco[idx];
        float no = fmaxf(od, co);
        float e1 = __expf(od - no);
        float e2 = __expf(co - no);
        a  = e1 * a + e2 * g_sca[idx];
        q  = e1 * q + e2 * g_scb[idx];
        oo = no;
    }
}

__global__ void wkv_segC(const float* __restrict__ time_decay,
                         const float* __restrict__ time_first) {
    int gid = blockIdx.x * blockDim.x + threadIdx.x;
    if (gid >= NSEGST) return;
    int c = gid & (CC - 1);
    int s = (gid >> 10) & (SEG - 1);
    int b = gid >> 13;

    float w = -__expf(time_decay[c]);
    float u = time_first[c];

    const float* kk = g_kvr;
    const float* vv = g_kvr + SZ;
    const float* rr = g_kvr + 2 * (size_t)SZ;

    float p = g_pa[gid];
    float q = g_pb[gid];
    float o = g_po[gid];
    int m0 = b * TT + s * SEGLEN;
    size_t off = (size_t)m0 * CC + c;

#pragma unroll 4
    for (int t = 0; t < SEGLEN; t++, off += CC) {
        float kt = kk[off];
        float vt = vv[off];
        float rt = rr[off];

        float uk = u + kt;
        float no = fmaxf(o, uk);
        float eA = __expf(o - no);
        float eB = __expf(uk - no);
        float y  = __fdividef(eA * p + eB * vt, eA * q + eB);

        float sr = __fdividef(1.f, 1.f + __expf(-rt));
        float f = sr * y;
        size_t bo = ablk(m0 + t, c);
        *(__half*)((char*)g_y_h + bo) = __float2half_rn(f);

        float wo  = w + o;
        float no2 = fmaxf(wo, kt);
        float A2  = __expf(wo - no2);
        float B2  = __expf(kt - no2);
        p = A2 * p + B2 * vt;
        q = A2 * q + B2;
        o = no2;
    }
}

// ---------------------------------------------------------------------------
extern "C" void kernel_launch(void* const* d_in, const int* in_sizes, int n_in,
                              void* d_out, int out_size) {
    const float* x   = (const float*)d_in[0];
    const float* td  = (const float*)d_in[1];
    const float* tf  = (const float*)d_in[2];
    const float* tmk = (const float*)d_in[3];
    const float* tmv = (const float*)d_in[4];
    const float* tmr = (const float*)d_in[5];
    const float* Wk  = (const float*)d_in[6];
    const float* Wv  = (const float*)d_in[7];
    const float* Wr  = (const float*)d_in[8];
    const float* Wo  = (const float*)d_in[9];
    float* out = (float*)d_out;

    static bool attr_set = false;
    if (!attr_set) {
        cudaFuncSetAttribute(gemm3_mma, cudaFuncAttributeMaxDynamicSharedMemorySize, SMEM_BYTES);
        cudaFuncSetAttribute(gemm_out_mma, cudaFuncAttributeMaxDynamicSharedMemorySize, SMEM_BYTES);
        attr_set = true;
    }

    const int n4 = SZ / 4;
    mix_kernel<<<(n4 + 255) / 256, 256>>>(x, tmk, tmv, tmr);
    wsplit_kernel<<<(WSZ + 255) / 256, 256>>>(Wk, Wv, Wr, Wo);

    dim3 g3(CC / CTA_N, MROWS / CTA_M, 3);
    gemm3_mma<<<g3, 256, SMEM_BYTES>>>();

    wkv_segA<<<(NSEGST + 255) / 256, 256>>>(td);
    wkv_segB<<<(BB * CC + 255) / 256, 256>>>(td);
    wkv_segC<<<(NSEGST + 255) / 256, 256>>>(td, tf);

    dim3 go(CC / CTA_N, MROWS / CTA_M, 1);
    gemm_out_mma<<<go, 256, SMEM_BYTES>>>(out);
}

// round 17
// speedup vs baseline: 3.9921x; 1.5783x over previous
#include <cuda_runtime.h>
#include <cuda_bf16.h>
#include <cuda_fp16.h>
#include <cstdint>

// RWKV TimeMix on GB300 (compute_103-safe tensor path):
//   mix(fp16, K-blocked+SW128 layout) -> 3x HMMA GEMM (bulk-copy 4-stage
//   pipeline, pure fp16 single-term) -> WKV 3-phase parallel scan -> out GEMM.
// GEMM: D[m,d] = sum_c A[m,c]*W[d,c], both operands fp16 (f32 accumulate).
// Error model (calibrated R16): A-quant 3.1e-4 + W-quant 3.1e-4 RMS ->
// combined ~4.4e-4 << 1e-3.

#define BB 32
#define TT 256
#define CC 1024
#define MROWS (BB * TT)                 // 8192
#define SZ (BB * TT * CC)               // 8,388,608
#define WSZ (CC * CC)                   // 1,048,576
#define SEG 8
#define SEGLEN (TT / SEG)               // 32
#define NSEGST (BB * SEG * CC)          // 262144

// ------------------------- device scratch (no allocs) -----------------------
__device__ __half g_a_h[3 * SZ];        // xk,xv,xr fp16, blocked+swizzled
__device__ __half g_w_h[4 * WSZ];       // W fp16, blocked+swizzled
__device__ float  g_kvr[3 * SZ];        // k,v,r fp32, linear [m][c]
__device__ __half g_y_h[SZ];            // gated y fp16, blocked+swizzled
__device__ float g_sca[NSEGST], g_scb[NSEGST], g_sco[NSEGST];
__device__ float g_pa[NSEGST],  g_pb[NSEGST],  g_po[NSEGST];

// ------------------------------ PTX helpers --------------------------------
__device__ __forceinline__ uint32_t smem_u32(const void* p) {
    uint32_t a;
    asm("{ .reg .u64 t; cvta.to.shared.u64 t, %1; cvt.u32.u64 %0, t; }"
        : "=r"(a) : "l"(p));
    return a;
}
__device__ __forceinline__ uint32_t sw128(uint32_t o) {
    return o ^ ((o >> 3) & 0x70);
}
__device__ __forceinline__ void bulk_g2s(uint32_t dst, const void* src,
                                         uint32_t bytes, uint32_t mbar) {
    asm volatile(
        "cp.async.bulk.shared::cluster.global.mbarrier::complete_tx::bytes "
        "[%0], [%1], %2, [%3];"
        :: "r"(dst), "l"(src), "r"(bytes), "r"(mbar) : "memory");
}
#define MBAR_INIT(mb, n) \
    asm volatile("mbarrier.init.shared.b64 [%0], %1;" :: "r"(mb), "r"(n) : "memory")
#define MBAR_EXPECT_TX(mb, bytes) \
    asm volatile("mbarrier.arrive.expect_tx.shared.b64 _, [%0], %1;" \
                 :: "r"(mb), "r"(bytes) : "memory")
#define MBAR_WAIT(mb, par) do {                                                   \
    uint32_t _m = (mb), _p = (par), _d;                                           \
    asm volatile("{ .reg .pred p;"                                                \
        " mbarrier.try_wait.parity.acquire.cta.shared::cta.b64 p, [%1], %2;"      \
        " selp.b32 %0,1,0,p; }" : "=r"(_d) : "r"(_m), "r"(_p) : "memory");        \
    if (!_d) {                                                                    \
        asm volatile("{ .reg .pred P;"                                            \
            "WL_%=: mbarrier.try_wait.parity.acquire.cta.shared::cta.b64 P, [%0], %1, 0x989680;" \
            " @P bra.uni WD_%=;  bra.uni WL_%=;  WD_%=: }"                        \
            :: "r"(_m), "r"(_p) : "memory");                                      \
    }                                                                             \
} while (0)

__device__ __forceinline__ void ldsm4(uint32_t* r, uint32_t a) {
    asm volatile("ldmatrix.sync.aligned.m8n8.x4.shared.b16 {%0,%1,%2,%3}, [%4];"
        : "=r"(r[0]), "=r"(r[1]), "=r"(r[2]), "=r"(r[3]) : "r"(a));
}
__device__ __forceinline__ void mma16816(float* c, const uint32_t* a, const uint32_t* b) {
    asm volatile("mma.sync.aligned.m16n8k16.row.col.f32.f16.f16.f32 "
        "{%0,%1,%2,%3}, {%4,%5,%6,%7}, {%8,%9}, {%0,%1,%2,%3};"
        : "+f"(c[0]), "+f"(c[1]), "+f"(c[2]), "+f"(c[3])
        : "r"(a[0]), "r"(a[1]), "r"(a[2]), "r"(a[3]), "r"(b[0]), "r"(b[1]));
}
// Pack two floats into fp16x2 (memory order: a low, b high).
__device__ __forceinline__ uint32_t pack_h2(float a, float b) {
    uint32_t h;
    asm("cvt.rn.f16x2.f32 %0, %1, %2;" : "=r"(h) : "f"(b), "f"(a));
    return h;
}

// Blocked-layout byte offsets (KCHUNK=64, 128B rows, SW128 baked in).
__device__ __forceinline__ size_t ablk(int m, int c) {     // activations / y
    uint32_t o = (uint32_t)m * 128 + (c & 63) * 2;
    return (size_t)(c >> 6) * (MROWS * 128) + sw128(o);
}
__device__ __forceinline__ size_t wblk(int n, int c) {     // weights
    uint32_t o = (uint32_t)n * 128 + (c & 63) * 2;
    return (size_t)(c >> 6) * (CC * 128) + sw128(o);
}

// ------------------------------ GEMM config --------------------------------
#define CTA_M 256
#define CTA_N 128
#define KCHUNK 64
#define NCHUNK (CC / KCHUNK)       // 16
#define NSTAGE 4
#define SM_AH 0
#define SM_WH 32768
#define STAGE 49152
#define CHUNK_BYTES 49152
#define SMEM_BYTES (NSTAGE * STAGE + 64)   // 196672

__device__ __forceinline__ void gemm_mma_body(
    const char* __restrict__ Ahb, const char* __restrict__ Whb,
    float* __restrict__ D)
{
    extern __shared__ char smem[];
    const uint32_t sb = smem_u32(smem);
    const uint32_t mbb = sb + NSTAGE * STAGE;   // four 8B mbarriers
    const int tid = threadIdx.x;
    const int wid = tid >> 5;
    const int lane = tid & 31;
    const int wm = wid >> 1;
    const int wn = wid & 1;
    const int gm = blockIdx.y * CTA_M;
    const int gn = blockIdx.x * CTA_N;

    if (tid == 0) {
        MBAR_INIT(mbb, 1); MBAR_INIT(mbb + 8, 1);
        MBAR_INIT(mbb + 16, 1); MBAR_INIT(mbb + 24, 1);
    }
    __syncthreads();

#define ISSUE(ck, s) do {                                                     \
    uint32_t _mb = mbb + 8 * (s);                                             \
    uint32_t _d  = sb + (s) * STAGE;                                          \
    MBAR_EXPECT_TX(_mb, CHUNK_BYTES);                                         \
    bulk_g2s(_d + SM_AH, Ahb + (size_t)(ck) * (MROWS * 128) + gm * 128, 32768, _mb); \
    bulk_g2s(_d + SM_WH, Whb + (size_t)(ck) * (CC * 128) + gn * 128, 16384, _mb);    \
} while (0)

    if (tid == 0) { ISSUE(0, 0); ISSUE(1, 1); ISSUE(2, 2); ISSUE(3, 3); }

    float acc[4][8][4];
#pragma unroll
    for (int i = 0; i < 4; i++)
#pragma unroll
        for (int j = 0; j < 8; j++)
#pragma unroll
            for (int q = 0; q < 4; q++) acc[i][j][q] = 0.f;

    const int a_row = wm * 64 + (lane & 7) + ((lane >> 3) & 1) * 8;  // + mi*16
    const int a_kof = (lane >> 4) * 8;                               // + k0
    const int b_row = wn * 64 + lane;                                // + g*32

    for (int ck = 0; ck < NCHUNK; ck++) {
        const int s = ck & (NSTAGE - 1);
        MBAR_WAIT(mbb + 8 * s, (ck >> 2) & 1);
        const uint32_t s0 = sb + s * STAGE;

#pragma unroll
        for (int k0 = 0; k0 < KCHUNK; k0 += 16) {
            uint32_t ah[4][4];
#pragma unroll
            for (int mi = 0; mi < 4; mi++) {
                uint32_t o = (uint32_t)(a_row + mi * 16) * 128 + (k0 + a_kof) * 2;
                ldsm4(ah[mi], s0 + SM_AH + sw128(o));
            }
#pragma unroll
            for (int g = 0; g < 2; g++) {
                uint32_t t0[4], t1[4];
                uint32_t o0 = (uint32_t)(b_row + g * 32) * 128 + k0 * 2;
                ldsm4(t0, s0 + SM_WH + sw128(o0));
                ldsm4(t1, s0 + SM_WH + sw128(o0 + 16));
#pragma unroll
                for (int ss = 0; ss < 4; ss++) {
                    uint32_t bh[2] = { t0[ss], t1[ss] };
#pragma unroll
                    for (int mi = 0; mi < 4; mi++)
                        mma16816(acc[mi][g * 4 + ss], ah[mi], bh);
                }
            }
        }
        __syncthreads();
        if (ck + NSTAGE < NCHUNK && tid == 0) ISSUE(ck + NSTAGE, s);
    }
#undef ISSUE

    const int trow = lane >> 2;
    const int tcol = (lane & 3) * 2;
#pragma unroll
    for (int mi = 0; mi < 4; mi++) {
#pragma unroll
        for (int ni = 0; ni < 8; ni++) {
            float* dp = D + (size_t)(gm + wm * 64 + mi * 16 + trow) * CC
                          + gn + wn * 64 + ni * 8 + tcol;
            float2 v0 = { acc[mi][ni][0], acc[mi][ni][1] };
            float2 v1 = { acc[mi][ni][2], acc[mi][ni][3] };
            *(float2*)dp = v0;
            *(float2*)(dp + 8 * CC) = v1;
        }
    }
}

__global__ __launch_bounds__(256, 1)
void gemm3_mma() {
    const int z = blockIdx.z;
    gemm_mma_body((const char*)g_a_h + (size_t)z * SZ * 2,
                  (const char*)g_w_h + (size_t)z * WSZ * 2,
                  g_kvr + (size_t)z * SZ);
}

__global__ __launch_bounds__(256, 1)
void gemm_out_mma(float* __restrict__ out) {
    gemm_mma_body((const char*)g_y_h,
                  (const char*)g_w_h + (size_t)3 * WSZ * 2, out);
}

// ------------------------------- mix kernel ---------------------------------
__global__ void mix_kernel(const float* __restrict__ x,
                           const float* __restrict__ tmk,
                           const float* __restrict__ tmv,
                           const float* __restrict__ tmr) {
    const int n4 = SZ / 4;
    int i = blockIdx.x * blockDim.x + threadIdx.x;
    if (i >= n4) return;
    const int cpt = CC / 4;
    int c4 = i & (cpt - 1);
    int m  = i >> 8;
    int t  = m & (TT - 1);
    int c  = c4 * 4;

    const float4* x4 = (const float4*)x;
    float4 xc = x4[i];
    float4 xp = make_float4(0.f, 0.f, 0.f, 0.f);
    if (t != 0) xp = x4[i - cpt];

    const float4 ms[3] = { ((const float4*)tmk)[c4],
                           ((const float4*)tmv)[c4],
                           ((const float4*)tmr)[c4] };
    const size_t off = ablk(m, c);
#pragma unroll
    for (int z = 0; z < 3; z++) {
        float4 mm = ms[z];
        float a  = xp.x + mm.x * (xc.x - xp.x);
        float b  = xp.y + mm.y * (xc.y - xp.y);
        float c2 = xp.z + mm.z * (xc.z - xp.z);
        float d  = xp.w + mm.w * (xc.w - xp.w);
        uint2 h;
        h.x = pack_h2(a, b);
        h.y = pack_h2(c2, d);
        *(uint2*)((char*)g_a_h + (size_t)z * SZ * 2 + off) = h;
    }
}

// --------------------------- weight convert kernel --------------------------
__global__ void wsplit_kernel(const float* __restrict__ Wk, const float* __restrict__ Wv,
                              const float* __restrict__ Wr, const float* __restrict__ Wo) {
    int i = blockIdx.x * blockDim.x + threadIdx.x;
    const int per = WSZ / 4;
    if (i >= 4 * per) return;
    int z = i >> 18;
    int loc = i & (per - 1);
    int n = loc >> 8;
    int c = (loc & 255) * 4;
    const float* W = (z == 0) ? Wk : (z == 1) ? Wv : (z == 2) ? Wr : Wo;
    float4 v = ((const float4*)W)[loc];
    uint2 h;
    h.x = pack_h2(v.x, v.y);
    h.y = pack_h2(v.z, v.w);
    const size_t off = wblk(n, c);
    *(uint2*)((char*)g_w_h + (size_t)z * WSZ * 2 + off) = h;
}

// ----------------------- WKV: 3-phase parallel scan -------------------------
__global__ void wkv_segA(const float* __restrict__ time_decay) {
    int gid = blockIdx.x * blockDim.x + threadIdx.x;
    if (gid >= NSEGST) return;
    int c = gid & (CC - 1);
    int s = (gid >> 10) & (SEG - 1);
    int b = gid >> 13;

    float w = -__expf(time_decay[c]);
    const float* kk = g_kvr;
    const float* vv = g_kvr + SZ;
    size_t off = ((size_t)(b * TT + s * SEGLEN)) * CC + c;

    float ca = 0.f, cb = 0.f, oo = -1e38f;
#pragma unroll 4
    for (int t = 0; t < SEGLEN; t++, off += CC) {
        float kt = kk[off];
        float vt = vv[off];
        float wo = w + oo;
        float no = fmaxf(wo, kt);
        float A2 = __expf(wo - no);
        float B2 = __expf(kt - no);
        ca = A2 * ca + B2 * vt;
        cb = A2 * cb + B2;
        oo = no;
    }
    g_sca[gid] = ca;
    g_scb[gid] = cb;
    g_sco[gid] = oo;
}

__global__ void wkv_segB(const float* __restrict__ time_decay) {
    int gid = blockIdx.x * blockDim.x + threadIdx.x;
    if (gid >= BB * CC) return;
    int c = gid & (CC - 1);
    int b = gid >> 10;

    float w = -__expf(time_decay[c]);
    float dec = (float)SEGLEN * w;

    float a = 0.f, q = 0.f, oo = -1e38f;
#pragma unroll
    for (int s = 0; s < SEG; s++) {
        int idx = (b * SEG + s) * CC + c;
        g_pa[idx] = a;
        g_pb[idx] = q;
        g_po[idx] = oo;
        float od = oo + dec;
        float co = g_sco[idx];
        float no = fmaxf(od, co);
        float e1 = __expf(od - no);
        float e2 = __expf(co - no);
        a  = e1 * a + e2 * g_sca[idx];
        q  = e1 * q + e2 * g_scb[idx];
        oo = no;
    }
}

__global__ void wkv_segC(const float* __restrict__ time_decay,
                         const float* __restrict__ time_first) {
    int gid = blockIdx.x * blockDim.x + threadIdx.x;
    if (gid >= NSEGST) return;
    int c = gid & (CC - 1);
    int s = (gid >> 10) & (SEG - 1);
    int b = gid >> 13;

    float w = -__expf(time_decay[c]);
    float u = time_first[c];

    const float* kk = g_kvr;
    const float* vv = g_kvr + SZ;
    const float* rr = g_kvr + 2 * (size_t)SZ;

    float p = g_pa[gid];
    float q = g_pb[gid];
    float o = g_po[gid];
    int m0 = b * TT + s * SEGLEN;
    size_t off = (size_t)m0 * CC + c;

#pragma unroll 4
    for (int t = 0; t < SEGLEN; t++, off += CC) {
        float kt = kk[off];
        float vt = vv[off];
        float rt = rr[off];

        float uk = u + kt;
        float no = fmaxf(o, uk);
        float eA = __expf(o - no);
        float eB = __expf(uk - no);
        float y  = __fdividef(eA * p + eB * vt, eA * q + eB);

        float sr = __fdividef(1.f, 1.f + __expf(-rt));
        float f = sr * y;
        size_t bo = ablk(m0 + t, c);
        *(__half*)((char*)g_y_h + bo) = __float2half_rn(f);

        float wo  = w + o;
        float no2 = fmaxf(wo, kt);
        float A2  = __expf(wo - no2);
        float B2  = __expf(kt - no2);
        p = A2 * p + B2 * vt;
        q = A2 * q + B2;
        o = no2;
    }
}

// ---------------------------------------------------------------------------
extern "C" void kernel_launch(void* const* d_in, const int* in_sizes, int n_in,
                              void* d_out, int out_size) {
    const float* x   = (const float*)d_in[0];
    const float* td  = (const float*)d_in[1];
    const float* tf  = (const float*)d_in[2];
    const float* tmk = (const float*)d_in[3];
    const float* tmv = (const float*)d_in[4];
    const float* tmr = (const float*)d_in[5];
    const float* Wk  = (const float*)d_in[6];
    const float* Wv  = (const float*)d_in[7];
    const float* Wr  = (const float*)d_in[8];
    const float* Wo  = (const float*)d_in[9];
    float* out = (float*)d_out;

    static bool attr_set = false;
    if (!attr_set) {
        cudaFuncSetAttribute(gemm3_mma, cudaFuncAttributeMaxDynamicSharedMemorySize, SMEM_BYTES);
        cudaFuncSetAttribute(gemm_out_mma, cudaFuncAttributeMaxDynamicSharedMemorySize, SMEM_BYTES);
        attr_set = true;
    }

    const int n4 = SZ / 4;
    mix_kernel<<<(n4 + 255) / 256, 256>>>(x, tmk, tmv, tmr);
    wsplit_kernel<<<(WSZ + 255) / 256, 256>>>(Wk, Wv, Wr, Wo);

    dim3 g3(CC / CTA_N, MROWS / CTA_M, 3);
    gemm3_mma<<<g3, 256, SMEM_BYTES>>>();

    wkv_segA<<<(NSEGST + 255) / 256, 256>>>(td);
    wkv_segB<<<(BB * CC + 255) / 256, 256>>>(td);
    wkv_segC<<<(NSEGST + 255) / 256, 256>>>(td, tf);

    dim3 go(CC / CTA_N, MROWS / CTA_M, 1);
    gemm_out_mma<<<go, 256, SMEM_BYTES>>>(out);
}